// round 13
// baseline (speedup 1.0000x reference)
#include <cuda_runtime.h>
#include <cuda_bf16.h>
#include <cstdint>
#include <cstddef>

// ---------------------------------------------------------------------------
// Word2vec NCE forward, split edition v4:
//   chunked cp.async fill overlapped under a register-pipelined HMMA mainloop.
//   out[0 .. BATCH*EMB) = embeddings[inputs]   (f32, exact gather)
//   out[BATCH*EMB]      = nce_cost
//
// Launch 1 gather_kernel (unchanged, ~5.7 TB/s effective).
// Launch 2 gemm_kernel: fill in 4 commit groups (A + B k-chunk0 first);
//   mainloop = 4 chunk loops, each wait_group + sync, then 4 k-steps with
//   A/B register double-buffering. Fill streams under compute.
// ---------------------------------------------------------------------------

namespace {
constexpr int VOCAB = 100000;
constexpr int EMB   = 256;
constexpr int NS    = 256;
constexpr int BATCH = 16384;
constexpr int TB    = 128;               // batch rows per gemm block
constexpr int NBLK2 = BATCH / TB;        // 128 gemm blocks
constexpr int NBLK1G = 256;              // embed-gather blocks
constexpr int NBLK1 = NBLK1G + 16;       // + wt-gather blocks
constexpr int NTHR2 = 512;

// gemm smem byte map
constexpr int SM_A    = 0;               // A: 128 x 256 bf16 = 64 KB (512B pitch, swizzled)
constexpr int SM_B    = 65536;           // B: 256 x 256 bf16 = 128 KB
constexpr int SM_SOFF = 196608;          // soff[256] f32
constexpr int SM_WSUM = 197632;          // 16 warp partials
constexpr int SM_TOT  = 197632 + 64;
}

__device__ __nv_bfloat16 g_wtb[NS * EMB];       // sampled weights [s][k] bf16
__device__ uint4    g_ab[BATCH * 32];           // embed rows, bf16 [r][k] (8 MB)
__device__ float    g_partial1[NBLK1G];
__device__ float    g_partial2[NBLK2];
__device__ unsigned g_done;                     // static-init 0; reset after use

// ---------------------------------------------------------------------------
__device__ __forceinline__ long long load_id(const void* p, int i, int is64) {
    return is64 ? ((const long long*)p)[i] : (long long)((const int*)p)[i];
}
__device__ __forceinline__ int detect_is64(const void* p) {
    const int* q = (const int*)p;
    int z = 0;
    #pragma unroll
    for (int i = 0; i < 16; i++) z |= q[2 * i + 1];
    return (z == 0) ? 1 : 0;
}
__device__ __forceinline__ uint32_t smem_u32(const void* p) {
    uint32_t a;
    asm("{ .reg .u64 t; cvta.to.shared.u64 t, %1; cvt.u32.u64 %0, t; }"
        : "=r"(a) : "l"(p));
    return a;
}
// [row][256 bf16] tile, 512B pitch, 16B chunks XOR-swizzled by row&7
__device__ __forceinline__ uint32_t t_sw(int row, int chunk) {
    return (uint32_t)row * 512u + (uint32_t)(((chunk ^ (row & 7)) & 31) << 4);
}
__device__ __forceinline__ void ldsm_x4(uint32_t addr, uint32_t* r) {
    asm volatile("ldmatrix.sync.aligned.m8n8.x4.shared.b16 {%0,%1,%2,%3}, [%4];"
        : "=r"(r[0]), "=r"(r[1]), "=r"(r[2]), "=r"(r[3]) : "r"(addr));
}
__device__ __forceinline__ void mma_bf16(float* c, const uint32_t* a,
                                         const uint32_t* b) {
    asm volatile(
        "mma.sync.aligned.m16n8k16.row.col.f32.bf16.bf16.f32 "
        "{%0,%1,%2,%3}, {%4,%5,%6,%7}, {%8,%9}, {%0,%1,%2,%3};"
        : "+f"(c[0]), "+f"(c[1]), "+f"(c[2]), "+f"(c[3])
        : "r"(a[0]), "r"(a[1]), "r"(a[2]), "r"(a[3]), "r"(b[0]), "r"(b[1]));
}
__device__ __forceinline__ void cp16(uint32_t dst, const void* src) {
    asm volatile("cp.async.cg.shared.global [%0], [%1], 16;"
                 :: "r"(dst), "l"(src) : "memory");
}
__device__ __forceinline__ void cp_commit() {
    asm volatile("cp.async.commit_group;" ::: "memory");
}
template <int N>
__device__ __forceinline__ void cp_wait() {
    asm volatile("cp.async.wait_group %0;" :: "n"(N) : "memory");
}
__device__ __forceinline__ float softplus_neg(float ax) {
    return __logf(1.0f + __expf(-ax));   // log1p(exp(-ax)), ax >= 0
}

// ---------------------------------------------------------------------------
// Launch 1: full-occupancy latency/bandwidth work (unchanged from r7/r10).
__global__ void gather_kernel(const float* __restrict__ emb,
                              const float* __restrict__ ncw,
                              const float* __restrict__ ncb,
                              const void* __restrict__ inputs,
                              const void* __restrict__ labels,
                              const void* __restrict__ sids,
                              float* __restrict__ out)
{
    const int b = blockIdx.x;

    if (b >= NBLK1G) {
        const int is64 = detect_is64(sids);
        int base = (b - NBLK1G) * 256 + threadIdx.x;     // 0..4095
        #pragma unroll
        for (int i = 0; i < 16; i++) {
            int t = base + i * 4096;                      // 0..65535
            int s = t >> 8, k = t & 255;
            long long id = load_id(sids, s, is64);
            g_wtb[s * EMB + k] = __float2bfloat16(ncw[(size_t)id * EMB + k]);
        }
        return;
    }

    const int tid  = threadIdx.x;
    const int wid  = tid >> 5;
    const int lane = tid & 31;
    const int is64 = detect_is64(inputs);
    const int wr   = (b * 8 + wid) * 8;
    const float INVL = 1.0f / logf((float)VOCAB + 1.0f);

    const float4* emb4 = (const float4*)emb;
    const float4* ncw4 = (const float4*)ncw;
    float4*       out4 = (float4*)out;

    long long g   = load_id(inputs, wr, is64);
    long long lab = load_id(labels, wr, is64);
    float4 e0 = emb4[(size_t)g * 64 + lane * 2];
    float4 e1 = emb4[(size_t)g * 64 + lane * 2 + 1];
    float4 w0 = ncw4[(size_t)lab * 64 + lane * 2];
    float4 w1 = ncw4[(size_t)lab * 64 + lane * 2 + 1];
    float  bb = ncb[lab];
    float  fl = (float)lab;

    float tsum = 0.0f;
    #pragma unroll
    for (int rr = 0; rr < 8; rr++) {
        const int r = wr + rr;
        float4 ce0 = e0, ce1 = e1, cw0 = w0, cw1 = w1;
        float  cb = bb, cfl = fl;
        if (rr < 7) {
            g   = load_id(inputs, r + 1, is64);
            lab = load_id(labels, r + 1, is64);
            e0 = emb4[(size_t)g * 64 + lane * 2];
            e1 = emb4[(size_t)g * 64 + lane * 2 + 1];
            w0 = ncw4[(size_t)lab * 64 + lane * 2];
            w1 = ncw4[(size_t)lab * 64 + lane * 2 + 1];
            bb = ncb[lab];
            fl = (float)lab;
        }
        out4[(size_t)r * 64 + lane * 2]     = ce0;
        out4[(size_t)r * 64 + lane * 2 + 1] = ce1;
        {
            __nv_bfloat162 p0 = __floats2bfloat162_rn(ce0.x, ce0.y);
            __nv_bfloat162 p1 = __floats2bfloat162_rn(ce0.z, ce0.w);
            __nv_bfloat162 p2 = __floats2bfloat162_rn(ce1.x, ce1.y);
            __nv_bfloat162 p3 = __floats2bfloat162_rn(ce1.z, ce1.w);
            uint4 u;
            u.x = *(uint32_t*)&p0;
            u.y = *(uint32_t*)&p1;
            u.z = *(uint32_t*)&p2;
            u.w = *(uint32_t*)&p3;
            g_ab[(size_t)r * 32 + lane] = u;
        }
        float d = ce0.x * cw0.x;
        d = fmaf(ce0.y, cw0.y, d); d = fmaf(ce0.z, cw0.z, d);
        d = fmaf(ce0.w, cw0.w, d); d = fmaf(ce1.x, cw1.x, d);
        d = fmaf(ce1.y, cw1.y, d); d = fmaf(ce1.z, cw1.z, d);
        d = fmaf(ce1.w, cw1.w, d);
        #pragma unroll
        for (int o = 16; o > 0; o >>= 1) d += __shfl_xor_sync(0xffffffffu, d, o);
        if (lane == 0) {
            float p  = (logf(cfl + 2.0f) - logf(cfl + 1.0f)) * INVL;
            float tl = d + cb - logf((float)NS * p);
            tsum += fmaxf(tl, 0.0f) - tl + softplus_neg(fabsf(tl));
        }
    }

    __shared__ float ws[8];
    if (lane == 0) ws[wid] = tsum;
    __syncthreads();
    if (tid == 0) {
        float t = 0.0f;
        #pragma unroll
        for (int i = 0; i < 8; i++) t += ws[i];
        g_partial1[b] = t;
    }
}

// ---------------------------------------------------------------------------
// Launch 2: chunked-fill + register-pipelined GEMM.
__global__ void __launch_bounds__(NTHR2, 1)
gemm_kernel(const float* __restrict__ ncb, const void* __restrict__ sids,
            float* __restrict__ out)
{
    extern __shared__ __align__(1024) char smem[];
    const uint32_t smb = smem_u32(smem);
    const int tid  = threadIdx.x;
    const int wid  = tid >> 5;
    const int lane = tid & 31;
    const int b0   = blockIdx.x * TB;
    const float INVL = 1.0f / logf((float)VOCAB + 1.0f);

    // ---- fill: group0 = A(all) + B k-chunk0; groups 1..3 = B k-chunks 1..3
    {
        const char* ab  = (const char*)(g_ab + (size_t)b0 * 32);
        const char* wtb = (const char*)g_wtb;
        #pragma unroll
        for (int i = 0; i < 8; i++) {
            int t = tid + i * NTHR2;             // A: 0..4095 chunks
            int r = t >> 5, c = t & 31;
            cp16(smb + SM_A + t_sw(r, c), ab + r * 512 + c * 16);
        }
        #pragma unroll
        for (int i = 0; i < 4; i++) {            // B k-chunk 0 (cols 0..7)
            int t = tid + i * NTHR2;             // 0..2047
            int s = t >> 3, c = t & 7;
            cp16(smb + SM_B + t_sw(s, c), wtb + s * 512 + c * 16);
        }
        cp_commit();
        #pragma unroll
        for (int kc = 1; kc < 4; kc++) {
            #pragma unroll
            for (int i = 0; i < 4; i++) {
                int t = tid + i * NTHR2;
                int s = t >> 3, c = (t & 7) + kc * 8;
                cp16(smb + SM_B + t_sw(s, c), wtb + s * 512 + c * 16);
            }
            cp_commit();
        }
    }

    // ---- sampled-logit offsets (overlaps fill)
    if (tid < NS) {
        const int is64s = detect_is64(sids);
        long long id = load_id(sids, tid, is64s);
        float fid = (float)id;
        float p = (logf(fid + 2.0f) - logf(fid + 1.0f)) * INVL;
        ((float*)(smem + SM_SOFF))[tid] = ncb[id] - logf((float)NS * p);
    }

    // ---- HMMA GEMM 128x256x256, warp grid 4m x 4n, warp tile 32x64
    const int wm = wid & 3;
    const int wn = wid >> 2;
    float acc[2][8][4];
    #pragma unroll
    for (int mt = 0; mt < 2; mt++)
        #pragma unroll
        for (int nt = 0; nt < 8; nt++)
            #pragma unroll
            for (int j = 0; j < 4; j++) acc[mt][nt][j] = 0.0f;

    const int amat  = lane >> 3;
    const int arow0 = wm * 32 + ((amat & 1) << 3) + (lane & 7);
    const int arow1 = arow0 + 16;
    const int aext  = amat >> 1;
    const uint32_t abase0 = smb + SM_A + (uint32_t)arow0 * 512u;
    const uint32_t abase1 = smb + SM_A + (uint32_t)arow1 * 512u;
    const int axor0 = arow0 & 7, axor1 = arow1 & 7;

    const int bg  = lane >> 3;
    const int bkh = bg & 1;
    int browp[4];
    #pragma unroll
    for (int ntp = 0; ntp < 4; ntp++)
        browp[ntp] = wn * 64 + (ntp * 2 + (bg >> 1)) * 8 + (lane & 7);

    uint32_t A0[2][4], A1[2][4], B[2][4][4];

    #pragma unroll
    for (int kc = 0; kc < 4; kc++) {
        // wait until groups 0..kc have landed, then sync
        if (kc == 0) cp_wait<3>();
        else if (kc == 1) cp_wait<2>();
        else if (kc == 2) cp_wait<1>();
        else cp_wait<0>();
        __syncthreads();

        // preload first k-step of this chunk
        {
            int ks0 = kc * 4;
            int ac = ks0 * 2 + aext;
            ldsm_x4(abase0 + (uint32_t)(((ac ^ axor0) & 31) << 4), A0[0]);
            ldsm_x4(abase1 + (uint32_t)(((ac ^ axor1) & 31) << 4), A1[0]);
            int bc = ks0 * 2 + bkh;
            #pragma unroll
            for (int ntp = 0; ntp < 4; ntp++)
                ldsm_x4(smb + SM_B + t_sw(browp[ntp], bc), B[0][ntp]);
        }

        #pragma unroll
        for (int ksl = 0; ksl < 4; ksl++) {
            const int ks  = kc * 4 + ksl;
            const int cur = ksl & 1;
            const int nxt = cur ^ 1;
            const bool more = (ksl < 3);

            if (more) {
                int ac = (ks + 1) * 2 + aext;
                ldsm_x4(abase0 + (uint32_t)(((ac ^ axor0) & 31) << 4), A0[nxt]);
                ldsm_x4(abase1 + (uint32_t)(((ac ^ axor1) & 31) << 4), A1[nxt]);
            }
            mma_bf16(acc[0][0], A0[cur], B[cur][0]);
            mma_bf16(acc[1][0], A1[cur], B[cur][0]);
            mma_bf16(acc[0][1], A0[cur], B[cur][0] + 2);
            mma_bf16(acc[1][1], A1[cur], B[cur][0] + 2);

            if (more) {
                int bc = (ks + 1) * 2 + bkh;
                ldsm_x4(smb + SM_B + t_sw(browp[0], bc), B[nxt][0]);
                ldsm_x4(smb + SM_B + t_sw(browp[1], bc), B[nxt][1]);
            }
            mma_bf16(acc[0][2], A0[cur], B[cur][1]);
            mma_bf16(acc[1][2], A1[cur], B[cur][1]);
            mma_bf16(acc[0][3], A0[cur], B[cur][1] + 2);
            mma_bf16(acc[1][3], A1[cur], B[cur][1] + 2);

            if (more) {
                int bc = (ks + 1) * 2 + bkh;
                ldsm_x4(smb + SM_B + t_sw(browp[2], bc), B[nxt][2]);
                ldsm_x4(smb + SM_B + t_sw(browp[3], bc), B[nxt][3]);
            }
            mma_bf16(acc[0][4], A0[cur], B[cur][2]);
            mma_bf16(acc[1][4], A1[cur], B[cur][2]);
            mma_bf16(acc[0][5], A0[cur], B[cur][2] + 2);
            mma_bf16(acc[1][5], A1[cur], B[cur][2] + 2);

            mma_bf16(acc[0][6], A0[cur], B[cur][3]);
            mma_bf16(acc[1][6], A1[cur], B[cur][3]);
            mma_bf16(acc[0][7], A0[cur], B[cur][3] + 2);
            mma_bf16(acc[1][7], A1[cur], B[cur][3] + 2);
        }
    }

    // ---- epilogue: relu-sum + batched-log softplus (8 terms per log)
    const float* soff = (const float*)(smem + SM_SOFF);
    float ssum = 0.0f;
    {
        const int colb = wn * 64 + ((lane & 3) << 1);
        #pragma unroll
        for (int nt = 0; nt < 8; nt++) {
            float s0 = soff[colb + nt * 8];
            float s1 = soff[colb + nt * 8 + 1];
            float prod = 1.0f;
            #pragma unroll
            for (int mt = 0; mt < 2; mt++) {
                float l0 = acc[mt][nt][0] + s0;
                float l1 = acc[mt][nt][1] + s1;
                float l2 = acc[mt][nt][2] + s0;
                float l3 = acc[mt][nt][3] + s1;
                ssum += fmaxf(l0, 0.0f) + fmaxf(l1, 0.0f)
                      + fmaxf(l2, 0.0f) + fmaxf(l3, 0.0f);
                float t0 = 1.0f + __expf(-fabsf(l0));
                float t1 = 1.0f + __expf(-fabsf(l1));
                float t2 = 1.0f + __expf(-fabsf(l2));
                float t3 = 1.0f + __expf(-fabsf(l3));
                prod *= (t0 * t1) * (t2 * t3);
            }
            ssum += __logf(prod);
        }
    }

    // ---- reduce: warp -> block
    #pragma unroll
    for (int o = 16; o > 0; o >>= 1) ssum += __shfl_xor_sync(0xffffffffu, ssum, o);
    if (lane == 0) ((float*)(smem + SM_WSUM))[wid] = ssum;
    __syncthreads();

    __shared__ int s_last;
    if (tid == 0) {
        float t = 0.0f;
        #pragma unroll
        for (int i = 0; i < 16; i++) t += ((float*)(smem + SM_WSUM))[i];
        g_partial2[blockIdx.x] = t;
        __threadfence();
        unsigned cnt = atomicAdd(&g_done, 1u);
        s_last = (cnt == (unsigned)(NBLK2 - 1)) ? 1 : 0;
    }
    __syncthreads();

    if (s_last && wid == 0) {
        float s = 0.0f;
        #pragma unroll
        for (int i = 0; i < NBLK1G / 32; i++) s += g_partial1[lane + i * 32];
        #pragma unroll
        for (int i = 0; i < NBLK2 / 32; i++)  s += g_partial2[lane + i * 32];
        #pragma unroll
        for (int o = 16; o > 0; o >>= 1) s += __shfl_xor_sync(0xffffffffu, s, o);
        if (lane == 0) {
            out[(size_t)BATCH * EMB] = s * (1.0f / (float)BATCH);
            g_done = 0u;                     // reset for next graph replay
            __threadfence();
        }
    }
}

// ---------------------------------------------------------------------------
extern "C" void kernel_launch(void* const* d_in, const int* in_sizes, int n_in,
                              void* d_out, int out_size) {
    const float* emb    = (const float*)d_in[0];
    const float* ncw    = (const float*)d_in[1];
    const float* ncb    = (const float*)d_in[2];
    const void*  inputs = d_in[3];
    const void*  labels = d_in[4];
    const void*  sids   = d_in[5];
    float* out = (float*)d_out;

    cudaFuncSetAttribute(gemm_kernel,
                         cudaFuncAttributeMaxDynamicSharedMemorySize, SM_TOT);

    gather_kernel<<<NBLK1, 256>>>(emb, ncw, ncb, inputs, labels, sids, out);
    gemm_kernel<<<NBLK2, NTHR2, SM_TOT>>>(ncb, sids, out);
}

// round 15
// speedup vs baseline: 1.0750x; 1.0750x over previous
#include <cuda_runtime.h>
#include <cuda_bf16.h>
#include <cstdint>
#include <cstddef>

// ---------------------------------------------------------------------------
// Word2vec NCE forward, split edition v5: 32-warp GEMM CTA (8 warps/SMSP).
//   out[0 .. BATCH*EMB) = embeddings[inputs]   (f32, exact gather)
//   out[BATCH*EMB]      = nce_cost
//
// Launch 1 gather_kernel (unchanged, ~5.7 TB/s effective).
// Launch 2 gemm_kernel: 1024 threads, warp grid 4m x 8n, warp tile 32x32,
//   single cp.async group fill, plain per-k-step LDSM+MMA (no reg double
//   buffering -- RF budget is 64 regs/thread), batched-log epilogue.
// ---------------------------------------------------------------------------

namespace {
constexpr int VOCAB = 100000;
constexpr int EMB   = 256;
constexpr int NS    = 256;
constexpr int BATCH = 16384;
constexpr int TB    = 128;               // batch rows per gemm block
constexpr int NBLK2 = BATCH / TB;        // 128 gemm blocks
constexpr int NBLK1G = 256;              // embed-gather blocks
constexpr int NBLK1 = NBLK1G + 16;       // + wt-gather blocks
constexpr int NTHR2 = 1024;              // 32 warps

// gemm smem byte map
constexpr int SM_A    = 0;               // A: 128 x 256 bf16 = 64 KB (512B pitch, swizzled)
constexpr int SM_B    = 65536;           // B: 256 x 256 bf16 = 128 KB
constexpr int SM_SOFF = 196608;          // soff[256] f32
constexpr int SM_WSUM = 197632;          // 32 warp partials
constexpr int SM_TOT  = 197632 + 192;
}

__device__ __nv_bfloat16 g_wtb[NS * EMB];       // sampled weights [s][k] bf16
__device__ uint4    g_ab[BATCH * 32];           // embed rows, bf16 [r][k] (8 MB)
__device__ float    g_partial1[NBLK1G];
__device__ float    g_partial2[NBLK2];
__device__ unsigned g_done;                     // static-init 0; reset after use

// ---------------------------------------------------------------------------
__device__ __forceinline__ long long load_id(const void* p, int i, int is64) {
    return is64 ? ((const long long*)p)[i] : (long long)((const int*)p)[i];
}
__device__ __forceinline__ int detect_is64(const void* p) {
    const int* q = (const int*)p;
    int z = 0;
    #pragma unroll
    for (int i = 0; i < 16; i++) z |= q[2 * i + 1];
    return (z == 0) ? 1 : 0;
}
__device__ __forceinline__ uint32_t smem_u32(const void* p) {
    uint32_t a;
    asm("{ .reg .u64 t; cvta.to.shared.u64 t, %1; cvt.u32.u64 %0, t; }"
        : "=r"(a) : "l"(p));
    return a;
}
// [row][256 bf16] tile, 512B pitch, 16B chunks XOR-swizzled by row&7
__device__ __forceinline__ uint32_t t_sw(int row, int chunk) {
    return (uint32_t)row * 512u + (uint32_t)(((chunk ^ (row & 7)) & 31) << 4);
}
__device__ __forceinline__ void ldsm_x4(uint32_t addr, uint32_t* r) {
    asm volatile("ldmatrix.sync.aligned.m8n8.x4.shared.b16 {%0,%1,%2,%3}, [%4];"
        : "=r"(r[0]), "=r"(r[1]), "=r"(r[2]), "=r"(r[3]) : "r"(addr));
}
__device__ __forceinline__ void mma_bf16(float* c, const uint32_t* a,
                                         const uint32_t* b) {
    asm volatile(
        "mma.sync.aligned.m16n8k16.row.col.f32.bf16.bf16.f32 "
        "{%0,%1,%2,%3}, {%4,%5,%6,%7}, {%8,%9}, {%0,%1,%2,%3};"
        : "+f"(c[0]), "+f"(c[1]), "+f"(c[2]), "+f"(c[3])
        : "r"(a[0]), "r"(a[1]), "r"(a[2]), "r"(a[3]), "r"(b[0]), "r"(b[1]));
}
__device__ __forceinline__ void cp16(uint32_t dst, const void* src) {
    asm volatile("cp.async.cg.shared.global [%0], [%1], 16;"
                 :: "r"(dst), "l"(src) : "memory");
}
__device__ __forceinline__ void cp_commit() {
    asm volatile("cp.async.commit_group;" ::: "memory");
}
__device__ __forceinline__ void cp_wait0() {
    asm volatile("cp.async.wait_group 0;" ::: "memory");
}
__device__ __forceinline__ float softplus_neg(float ax) {
    return __logf(1.0f + __expf(-ax));   // log1p(exp(-ax)), ax >= 0
}

// ---------------------------------------------------------------------------
// Launch 1: full-occupancy latency/bandwidth work (unchanged from r7/r10).
__global__ void gather_kernel(const float* __restrict__ emb,
                              const float* __restrict__ ncw,
                              const float* __restrict__ ncb,
                              const void* __restrict__ inputs,
                              const void* __restrict__ labels,
                              const void* __restrict__ sids,
                              float* __restrict__ out)
{
    const int b = blockIdx.x;

    if (b >= NBLK1G) {
        const int is64 = detect_is64(sids);
        int base = (b - NBLK1G) * 256 + threadIdx.x;     // 0..4095
        #pragma unroll
        for (int i = 0; i < 16; i++) {
            int t = base + i * 4096;                      // 0..65535
            int s = t >> 8, k = t & 255;
            long long id = load_id(sids, s, is64);
            g_wtb[s * EMB + k] = __float2bfloat16(ncw[(size_t)id * EMB + k]);
        }
        return;
    }

    const int tid  = threadIdx.x;
    const int wid  = tid >> 5;
    const int lane = tid & 31;
    const int is64 = detect_is64(inputs);
    const int wr   = (b * 8 + wid) * 8;
    const float INVL = 1.0f / logf((float)VOCAB + 1.0f);

    const float4* emb4 = (const float4*)emb;
    const float4* ncw4 = (const float4*)ncw;
    float4*       out4 = (float4*)out;

    long long g   = load_id(inputs, wr, is64);
    long long lab = load_id(labels, wr, is64);
    float4 e0 = emb4[(size_t)g * 64 + lane * 2];
    float4 e1 = emb4[(size_t)g * 64 + lane * 2 + 1];
    float4 w0 = ncw4[(size_t)lab * 64 + lane * 2];
    float4 w1 = ncw4[(size_t)lab * 64 + lane * 2 + 1];
    float  bb = ncb[lab];
    float  fl = (float)lab;

    float tsum = 0.0f;
    #pragma unroll
    for (int rr = 0; rr < 8; rr++) {
        const int r = wr + rr;
        float4 ce0 = e0, ce1 = e1, cw0 = w0, cw1 = w1;
        float  cb = bb, cfl = fl;
        if (rr < 7) {
            g   = load_id(inputs, r + 1, is64);
            lab = load_id(labels, r + 1, is64);
            e0 = emb4[(size_t)g * 64 + lane * 2];
            e1 = emb4[(size_t)g * 64 + lane * 2 + 1];
            w0 = ncw4[(size_t)lab * 64 + lane * 2];
            w1 = ncw4[(size_t)lab * 64 + lane * 2 + 1];
            bb = ncb[lab];
            fl = (float)lab;
        }
        out4[(size_t)r * 64 + lane * 2]     = ce0;
        out4[(size_t)r * 64 + lane * 2 + 1] = ce1;
        {
            __nv_bfloat162 p0 = __floats2bfloat162_rn(ce0.x, ce0.y);
            __nv_bfloat162 p1 = __floats2bfloat162_rn(ce0.z, ce0.w);
            __nv_bfloat162 p2 = __floats2bfloat162_rn(ce1.x, ce1.y);
            __nv_bfloat162 p3 = __floats2bfloat162_rn(ce1.z, ce1.w);
            uint4 u;
            u.x = *(uint32_t*)&p0;
            u.y = *(uint32_t*)&p1;
            u.z = *(uint32_t*)&p2;
            u.w = *(uint32_t*)&p3;
            g_ab[(size_t)r * 32 + lane] = u;
        }
        float d = ce0.x * cw0.x;
        d = fmaf(ce0.y, cw0.y, d); d = fmaf(ce0.z, cw0.z, d);
        d = fmaf(ce0.w, cw0.w, d); d = fmaf(ce1.x, cw1.x, d);
        d = fmaf(ce1.y, cw1.y, d); d = fmaf(ce1.z, cw1.z, d);
        d = fmaf(ce1.w, cw1.w, d);
        #pragma unroll
        for (int o = 16; o > 0; o >>= 1) d += __shfl_xor_sync(0xffffffffu, d, o);
        if (lane == 0) {
            float p  = (logf(cfl + 2.0f) - logf(cfl + 1.0f)) * INVL;
            float tl = d + cb - logf((float)NS * p);
            tsum += fmaxf(tl, 0.0f) - tl + softplus_neg(fabsf(tl));
        }
    }

    __shared__ float ws[8];
    if (lane == 0) ws[wid] = tsum;
    __syncthreads();
    if (tid == 0) {
        float t = 0.0f;
        #pragma unroll
        for (int i = 0; i < 8; i++) t += ws[i];
        g_partial1[b] = t;
    }
}

// ---------------------------------------------------------------------------
// Launch 2: 32-warp GEMM (8 warps/SMSP), warp tile 32x32.
__global__ void __launch_bounds__(NTHR2, 1)
gemm_kernel(const float* __restrict__ ncb, const void* __restrict__ sids,
            float* __restrict__ out)
{
    extern __shared__ __align__(1024) char smem[];
    const uint32_t smb = smem_u32(smem);
    const int tid  = threadIdx.x;
    const int wid  = tid >> 5;
    const int lane = tid & 31;
    const int b0   = blockIdx.x * TB;
    const float INVL = 1.0f / logf((float)VOCAB + 1.0f);

    // ---- fill A + B via one cp.async group
    {
        const char* ab  = (const char*)(g_ab + (size_t)b0 * 32);
        const char* wtb = (const char*)g_wtb;
        #pragma unroll
        for (int i = 0; i < 4; i++) {
            int t = tid + i * NTHR2;             // A: 0..4095 chunks
            int r = t >> 5, c = t & 31;
            cp16(smb + SM_A + t_sw(r, c), ab + r * 512 + c * 16);
        }
        #pragma unroll
        for (int i = 0; i < 8; i++) {
            int t = tid + i * NTHR2;             // B: 0..8191 chunks
            int s = t >> 5, c = t & 31;
            cp16(smb + SM_B + t_sw(s, c), wtb + s * 512 + c * 16);
        }
        cp_commit();
    }

    // ---- sampled-logit offsets (overlaps fill)
    if (tid < NS) {
        const int is64s = detect_is64(sids);
        long long id = load_id(sids, tid, is64s);
        float fid = (float)id;
        float p = (logf(fid + 2.0f) - logf(fid + 1.0f)) * INVL;
        ((float*)(smem + SM_SOFF))[tid] = ncb[id] - logf((float)NS * p);
    }

    cp_wait0();
    __syncthreads();

    // ---- HMMA GEMM 128x256x256, warp grid 4m x 8n, warp tile 32x32
    const int wm = wid & 3;                      // m-group (32 rows)
    const int wn = wid >> 2;                     // n-group (32 cols), 0..7
    float acc[2][4][4];
    #pragma unroll
    for (int mt = 0; mt < 2; mt++)
        #pragma unroll
        for (int nt = 0; nt < 4; nt++)
            #pragma unroll
            for (int j = 0; j < 4; j++) acc[mt][nt][j] = 0.0f;

    const int amat  = lane >> 3;
    const int arow0 = wm * 32 + ((amat & 1) << 3) + (lane & 7);
    const int arow1 = arow0 + 16;
    const int aext  = amat >> 1;
    const uint32_t abase0 = smb + SM_A + (uint32_t)arow0 * 512u;
    const uint32_t abase1 = smb + SM_A + (uint32_t)arow1 * 512u;
    const int axor0 = arow0 & 7, axor1 = arow1 & 7;

    // B: 2 paired x4 loads cover 4 n-tiles (32 cols)
    const int bg  = lane >> 3;
    const int bkh = bg & 1;
    int browp[2];
    #pragma unroll
    for (int ntp = 0; ntp < 2; ntp++)
        browp[ntp] = wn * 32 + (ntp * 2 + (bg >> 1)) * 8 + (lane & 7);

    #pragma unroll
    for (int ks = 0; ks < 16; ks++) {
        uint32_t a0[4], a1[4], b0f[4], b1f[4];
        int ac = ks * 2 + aext;
        ldsm_x4(abase0 + (uint32_t)(((ac ^ axor0) & 31) << 4), a0);
        ldsm_x4(abase1 + (uint32_t)(((ac ^ axor1) & 31) << 4), a1);
        int bc = ks * 2 + bkh;
        ldsm_x4(smb + SM_B + t_sw(browp[0], bc), b0f);
        ldsm_x4(smb + SM_B + t_sw(browp[1], bc), b1f);

        mma_bf16(acc[0][0], a0, b0f);
        mma_bf16(acc[1][0], a1, b0f);
        mma_bf16(acc[0][1], a0, b0f + 2);
        mma_bf16(acc[1][1], a1, b0f + 2);
        mma_bf16(acc[0][2], a0, b1f);
        mma_bf16(acc[1][2], a1, b1f);
        mma_bf16(acc[0][3], a0, b1f + 2);
        mma_bf16(acc[1][3], a1, b1f + 2);
    }

    // ---- epilogue: relu-sum + batched-log softplus
    const float* soff = (const float*)(smem + SM_SOFF);
    float ssum = 0.0f;
    {
        const int colb = wn * 32 + ((lane & 3) << 1);
        #pragma unroll
        for (int nt = 0; nt < 4; nt++) {
            float s0 = soff[colb + nt * 8];
            float s1 = soff[colb + nt * 8 + 1];
            float prod = 1.0f;
            #pragma unroll
            for (int mt = 0; mt < 2; mt++) {
                float l0 = acc[mt][nt][0] + s0;
                float l1 = acc[mt][nt][1] + s1;
                float l2 = acc[mt][nt][2] + s0;
                float l3 = acc[mt][nt][3] + s1;
                ssum += fmaxf(l0, 0.0f) + fmaxf(l1, 0.0f)
                      + fmaxf(l2, 0.0f) + fmaxf(l3, 0.0f);
                float t0 = 1.0f + __expf(-fabsf(l0));
                float t1 = 1.0f + __expf(-fabsf(l1));
                float t2 = 1.0f + __expf(-fabsf(l2));
                float t3 = 1.0f + __expf(-fabsf(l3));
                prod *= (t0 * t1) * (t2 * t3);
            }
            ssum += __logf(prod);
        }
    }

    // ---- reduce: warp -> block
    #pragma unroll
    for (int o = 16; o > 0; o >>= 1) ssum += __shfl_xor_sync(0xffffffffu, ssum, o);
    if (lane == 0) ((float*)(smem + SM_WSUM))[wid] = ssum;
    __syncthreads();

    __shared__ int s_last;
    if (tid == 0) {
        float t = 0.0f;
        #pragma unroll
        for (int i = 0; i < 32; i++) t += ((float*)(smem + SM_WSUM))[i];
        g_partial2[blockIdx.x] = t;
        __threadfence();
        unsigned cnt = atomicAdd(&g_done, 1u);
        s_last = (cnt == (unsigned)(NBLK2 - 1)) ? 1 : 0;
    }
    __syncthreads();

    if (s_last && wid == 0) {
        float s = 0.0f;
        #pragma unroll
        for (int i = 0; i < NBLK1G / 32; i++) s += g_partial1[lane + i * 32];
        #pragma unroll
        for (int i = 0; i < NBLK2 / 32; i++)  s += g_partial2[lane + i * 32];
        #pragma unroll
        for (int o = 16; o > 0; o >>= 1) s += __shfl_xor_sync(0xffffffffu, s, o);
        if (lane == 0) {
            out[(size_t)BATCH * EMB] = s * (1.0f / (float)BATCH);
            g_done = 0u;                     // reset for next graph replay
            __threadfence();
        }
    }
}

// ---------------------------------------------------------------------------
extern "C" void kernel_launch(void* const* d_in, const int* in_sizes, int n_in,
                              void* d_out, int out_size) {
    const float* emb    = (const float*)d_in[0];
    const float* ncw    = (const float*)d_in[1];
    const float* ncb    = (const float*)d_in[2];
    const void*  inputs = d_in[3];
    const void*  labels = d_in[4];
    const void*  sids   = d_in[5];
    float* out = (float*)d_out;

    cudaFuncSetAttribute(gemm_kernel,
                         cudaFuncAttributeMaxDynamicSharedMemorySize, SM_TOT);

    gather_kernel<<<NBLK1, 256>>>(emb, ncw, ncb, inputs, labels, sids, out);
    gemm_kernel<<<NBLK2, NTHR2, SM_TOT>>>(ncb, sids, out);
}